// round 6
// baseline (speedup 1.0000x reference)
#include <cuda_runtime.h>

// Decoder: 48-step attention + GRU.  B=128, T=48, I=128, H=512.
//
// Restructuring vs reference:
//   - w2 = decoder_x @ W2^T + b2 precomputed once ([128,48,512]).
//   - M = W_ih @ W4  ([1536,131]) and bM = W_ih@b4 + b_ih precomputed once,
//     so gi = u @ M^T + bM  (exact algebraic fusion of two GEMMs).
// Per step (3 kernels):
//   A: hw = h @ [W1 ; W_hh]^T   (column-tiled x 2 k-split partials)
//   B: per-batch attention: w1=hwA+hwB+b1, e=tanh(w1+w2)@W3, softmax,
//      context c, u=[c, x_t] stored transposed as uT[k][b]
//   C: gi = u@M^T + bM, gates with gh = hwA+hwB(+b_hh), h <- GRU update
// Finale: re = h @ Wfc^T + bfc.
// Output layout: d_out[0:128] = re, d_out[128 : 128+6144] = alpha (last step).

#define BB 128
#define TT 48
#define II 128
#define HH 512
#define G3H 1536   // 3*H
#define CW 2048    // H + 3H columns of hw
#define UK 131     // I + 3
#define MST 132    // padded stride for M / uT rows

// ---------------- device scratch (static, no runtime allocation) -----------
__device__ float g_w2[BB * TT * HH];     // 12.6 MB
__device__ float g_M[G3H * MST];         // fused W_ih @ W4
__device__ float g_bM[G3H];              // W_ih @ b4 + b_ih
__device__ float g_h[BB * HH];           // hidden state (updated in place)
__device__ float g_hwA[BB * CW];         // k-half 0 partial of h @ Wcomb^T
__device__ float g_hwB[BB * CW];         // k-half 1 partial
__device__ float g_uT[MST * BB];         // u transposed: uT[k][b]

// ---------------- fast math helpers ----------------------------------------
__device__ __forceinline__ float fast_tanh(float x) {
    float e = __expf(2.0f * x);
    return 1.0f - __fdividef(2.0f, e + 1.0f);
}
__device__ __forceinline__ float fast_sigmoid(float x) {
    return __fdividef(1.0f, 1.0f + __expf(-x));
}

// ---------------- init hidden state ----------------------------------------
__global__ __launch_bounds__(256) void init_h_kernel(const float* __restrict__ h0) {
    int i = blockIdx.x * 256 + threadIdx.x;
    if (i < BB * HH) g_h[i] = h0[i];
}

// ---------------- precompute M = W_ih @ W4, bM = W_ih @ b4 + b_ih ----------
// grid 192 blocks, each handles 8 rows of M. threads j<132 (131 cols + bias).
__global__ __launch_bounds__(256) void precompute_M_kernel(
    const float* __restrict__ W_ih, const float* __restrict__ W4,
    const float* __restrict__ b4,   const float* __restrict__ b_ih) {
    __shared__ float sW[8][HH + 1];
    int g0 = blockIdx.x * 8;
    int tid = threadIdx.x;
    for (int i = tid; i < 8 * HH; i += 256) {
        int r = i >> 9, h = i & (HH - 1);
        sW[r][h] = W_ih[(g0 + r) * HH + h];
    }
    __syncthreads();
    int j = tid;
    if (j < 132) {
        float acc[8];
#pragma unroll
        for (int r = 0; r < 8; r++) acc[r] = 0.0f;
        for (int h = 0; h < HH; h++) {
            float bv = (j < UK) ? W4[h * UK + j] : b4[h];
#pragma unroll
            for (int r = 0; r < 8; r++) acc[r] += sW[r][h] * bv;
        }
#pragma unroll
        for (int r = 0; r < 8; r++) {
            int g = g0 + r;
            if (j < UK) g_M[g * MST + j] = acc[r];
            else        g_bM[g] = acc[r] + b_ih[g];
        }
    }
}

// ---------------- precompute w2[b,t,h] = dx[b,t,:] . W2[h,:] + b2[h] -------
// grid (96, 8): 64x64 output tiles of the [6144, 512] matrix, K=128.
__global__ __launch_bounds__(256) void precompute_w2_kernel(
    const float* __restrict__ dx, const float* __restrict__ W2,
    const float* __restrict__ b2) {
    __shared__ float As[64][65];
    __shared__ float Bs[64][65];
    int r0 = blockIdx.x * 64;
    int c0 = blockIdx.y * 64;
    int tid = threadIdx.x;
    int tx = tid & 15, ty = tid >> 4;        // tx: col group, ty: row group
    int c4 = tx * 4, r4 = ty * 4;
    float acc[4][4];
#pragma unroll
    for (int i = 0; i < 4; i++)
#pragma unroll
        for (int j = 0; j < 4; j++) acc[i][j] = 0.0f;

    for (int kc = 0; kc < 2; kc++) {
        int k0 = kc * 64;
        for (int i = tid; i < 64 * 64; i += 256) {
            int r = i >> 6, kk = i & 63;
            As[r][kk] = dx[(r0 + r) * II + k0 + kk];
            Bs[r][kk] = W2[(c0 + r) * II + k0 + kk];
        }
        __syncthreads();
#pragma unroll 8
        for (int kk = 0; kk < 64; kk++) {
            float w0 = Bs[c4 + 0][kk], w1 = Bs[c4 + 1][kk];
            float w2 = Bs[c4 + 2][kk], w3 = Bs[c4 + 3][kk];
#pragma unroll
            for (int i = 0; i < 4; i++) {
                float hv = As[r4 + i][kk];
                acc[i][0] += hv * w0; acc[i][1] += hv * w1;
                acc[i][2] += hv * w2; acc[i][3] += hv * w3;
            }
        }
        __syncthreads();
    }
#pragma unroll
    for (int i = 0; i < 4; i++)
#pragma unroll
        for (int j = 0; j < 4; j++)
            g_w2[(r0 + r4 + i) * HH + c0 + c4 + j] = acc[i][j] + b2[c0 + c4 + j];
}

// ---------------- step A: hw = h @ [W1 ; W_hh]^T ---------------------------
// 128 blocks = 64 column tiles (32 cols) x 2 k-halves (256 k each).
__global__ __launch_bounds__(256) void stepA_kernel(
    const float* __restrict__ W1, const float* __restrict__ W_hh) {
    __shared__ float HS[128][33];
    __shared__ float WS[32][33];
    int bid = blockIdx.x;
    int ct = bid & 63, kt = bid >> 6;
    int c0 = ct * 32;
    int kbase = kt * 256;
    float* out = kt ? g_hwB : g_hwA;
    int tid = threadIdx.x;
    int tx = tid & 7, ty = tid >> 3;
    int c4 = tx * 4, r4 = ty * 4;
    float acc[4][4];
#pragma unroll
    for (int i = 0; i < 4; i++)
#pragma unroll
        for (int j = 0; j < 4; j++) acc[i][j] = 0.0f;

    for (int kc = 0; kc < 8; kc++) {
        int k0 = kbase + kc * 32;
        for (int i = tid; i < 128 * 32; i += 256) {
            int r = i >> 5, kk = i & 31;
            HS[r][kk] = g_h[r * HH + k0 + kk];
        }
        for (int i = tid; i < 32 * 32; i += 256) {
            int c = i >> 5, kk = i & 31;
            int gc = c0 + c;
            const float* wrow = (gc < HH) ? (W1 + gc * HH) : (W_hh + (gc - HH) * HH);
            WS[c][kk] = wrow[k0 + kk];
        }
        __syncthreads();
#pragma unroll 8
        for (int kk = 0; kk < 32; kk++) {
            float w0 = WS[c4 + 0][kk], w1 = WS[c4 + 1][kk];
            float w2 = WS[c4 + 2][kk], w3 = WS[c4 + 3][kk];
#pragma unroll
            for (int i = 0; i < 4; i++) {
                float hv = HS[r4 + i][kk];
                acc[i][0] += hv * w0; acc[i][1] += hv * w1;
                acc[i][2] += hv * w2; acc[i][3] += hv * w3;
            }
        }
        __syncthreads();
    }
#pragma unroll
    for (int i = 0; i < 4; i++)
#pragma unroll
        for (int j = 0; j < 4; j++)
            out[(r4 + i) * CW + c0 + c4 + j] = acc[i][j];
}

// ---------------- step B: attention + context + uT -------------------------
// 128 blocks, one per batch element b.
__global__ __launch_bounds__(256) void stepB_kernel(
    const float* __restrict__ dx, const float* __restrict__ xin,
    const float* __restrict__ W3, const float* __restrict__ b1,
    const float* __restrict__ b3, float* __restrict__ out, int step) {
    __shared__ float w1s[HH];
    __shared__ float w3s[HH];
    __shared__ float es[TT];
    int b = blockIdx.x;
    int tid = threadIdx.x;
    for (int i = tid; i < HH; i += 256) {
        w1s[i] = g_hwA[b * CW + i] + g_hwB[b * CW + i] + b1[i];
        w3s[i] = W3[i];
    }
    __syncthreads();

    int warp = tid >> 5, lane = tid & 31;
    float b3v = b3[0];
    for (int j = 0; j < 6; j++) {
        int t = warp * 6 + j;
        const float* w2p = g_w2 + (b * TT + t) * HH;
        float p = 0.0f;
#pragma unroll 4
        for (int h = lane; h < HH; h += 32)
            p += fast_tanh(w1s[h] + w2p[h]) * w3s[h];
#pragma unroll
        for (int o = 16; o > 0; o >>= 1) p += __shfl_down_sync(0xffffffffu, p, o);
        if (lane == 0) es[t] = p + b3v;
    }
    __syncthreads();

    if (warp == 0) {
        float m = -1e30f;
        for (int i = lane; i < TT; i += 32) m = fmaxf(m, es[i]);
#pragma unroll
        for (int o = 16; o > 0; o >>= 1) m = fmaxf(m, __shfl_xor_sync(0xffffffffu, m, o));
        float s = 0.0f;
        for (int i = lane; i < TT; i += 32) { float e = __expf(es[i] - m); es[i] = e; s += e; }
#pragma unroll
        for (int o = 16; o > 0; o >>= 1) s += __shfl_xor_sync(0xffffffffu, s, o);
        float inv = __fdividef(1.0f, s);
        for (int i = lane; i < TT; i += 32) es[i] *= inv;
    }
    __syncthreads();

    if (tid < II) {
        const float* dp = dx + b * TT * II + tid;
        float acc = 0.0f;
#pragma unroll 4
        for (int t = 0; t < TT; t++) acc += dp[t * II] * es[t];
        g_uT[tid * BB + b] = acc;                 // uT[k][b], k = 0..127
    } else if (tid < UK) {
        int j = tid - II;
        g_uT[(II + j) * BB + b] = xin[(b * TT + step) * 3 + j];   // k = 128..130
    }
    if (step == TT - 1 && tid < TT)
        out[BB + b * TT + tid] = es[tid];         // alpha of last step
}

// ---------------- step C: gi = u @ M^T + bM, GRU gates, h update -----------
// 128 blocks; block j handles h-columns [4j, 4j+4).
__global__ __launch_bounds__(256) void stepC_kernel(const float* __restrict__ b_hh) {
    __shared__ float Ms[12][MST];
    __shared__ __align__(16) float us[32][BB];
    int jb = blockIdx.x;
    int c0 = jb * 4;
    int tid = threadIdx.x;
    // Ms row rr = g4*3 + gate  -> global M row gate*512 + c0 + g4
    for (int i = tid; i < 12 * MST; i += 256) {
        int rr = i / MST, k = i - rr * MST;
        int g4 = rr / 3, gate = rr - g4 * 3;
        int gr = gate * HH + c0 + g4;
        Ms[rr][k] = (k < UK) ? g_M[gr * MST + k] : 0.0f;
    }
    __syncthreads();

    int bp = tid & 63;        // batch pair index: rows 2bp, 2bp+1
    int g4 = tid >> 6;        // 0..3 -> which of the 4 h-columns
    float acc[2][3];
#pragma unroll
    for (int bi = 0; bi < 2; bi++)
#pragma unroll
        for (int g = 0; g < 3; g++) acc[bi][g] = 0.0f;

    for (int kc = 0; kc < 5; kc++) {
        int kbase = kc * 32;
        for (int i = tid; i < 32 * BB; i += 256) {
            int kk = i >> 7, bb = i & 127;
            int kg = kbase + kk;
            us[kk][bb] = (kg < UK) ? g_uT[kg * BB + bb] : 0.0f;
        }
        __syncthreads();
        int kmax = UK - kbase; if (kmax > 32) kmax = 32;
#pragma unroll 8
        for (int kk = 0; kk < kmax; kk++) {
            float2 uv = *(const float2*)&us[kk][bp * 2];
            int kg = kbase + kk;
            float m0 = Ms[g4 * 3 + 0][kg];
            float m1 = Ms[g4 * 3 + 1][kg];
            float m2 = Ms[g4 * 3 + 2][kg];
            acc[0][0] += uv.x * m0; acc[0][1] += uv.x * m1; acc[0][2] += uv.x * m2;
            acc[1][0] += uv.y * m0; acc[1][1] += uv.y * m1; acc[1][2] += uv.y * m2;
        }
        __syncthreads();
    }

    int c = c0 + g4;
#pragma unroll
    for (int bi = 0; bi < 2; bi++) {
        int b = bp * 2 + bi;
        float gir = acc[bi][0] + g_bM[c];
        float giz = acc[bi][1] + g_bM[HH + c];
        float gin = acc[bi][2] + g_bM[2 * HH + c];
        const float* hA = g_hwA + b * CW + HH;
        const float* hB = g_hwB + b * CW + HH;
        float ghr = hA[c]           + hB[c]           + b_hh[c];
        float ghz = hA[HH + c]      + hB[HH + c]      + b_hh[HH + c];
        float ghn = hA[2 * HH + c]  + hB[2 * HH + c]  + b_hh[2 * HH + c];
        float r = fast_sigmoid(gir + ghr);
        float z = fast_sigmoid(giz + ghz);
        float n = fast_tanh(gin + r * ghn);
        float hold = g_h[b * HH + c];
        g_h[b * HH + c] = (1.0f - z) * n + z * hold;
    }
}

// ---------------- finale: re = h @ Wfc^T + bfc ------------------------------
__global__ __launch_bounds__(256) void final_kernel(
    const float* __restrict__ Wfc, const float* __restrict__ bfc,
    float* __restrict__ out) {
    __shared__ float red[8];
    int b = blockIdx.x;
    int tid = threadIdx.x;
    int warp = tid >> 5, lane = tid & 31;
    float p = 0.0f;
    for (int h = tid; h < HH; h += 256) p += g_h[b * HH + h] * Wfc[h];
#pragma unroll
    for (int o = 16; o > 0; o >>= 1) p += __shfl_down_sync(0xffffffffu, p, o);
    if (lane == 0) red[warp] = p;
    __syncthreads();
    if (tid == 0) {
        float s = 0.0f;
#pragma unroll
        for (int w = 0; w < 8; w++) s += red[w];
        out[b] = s + bfc[0];
    }
}

// ---------------- launcher --------------------------------------------------
extern "C" void kernel_launch(void* const* d_in, const int* in_sizes, int n_in,
                              void* d_out, int out_size) {
    (void)in_sizes; (void)n_in; (void)out_size;
    const float* dx   = (const float*)d_in[0];
    const float* xin  = (const float*)d_in[1];
    const float* h0   = (const float*)d_in[2];
    const float* W1   = (const float*)d_in[3];
    const float* b1   = (const float*)d_in[4];
    const float* W2   = (const float*)d_in[5];
    const float* b2   = (const float*)d_in[6];
    const float* W3   = (const float*)d_in[7];
    const float* b3   = (const float*)d_in[8];
    const float* W4   = (const float*)d_in[9];
    const float* b4   = (const float*)d_in[10];
    const float* W_ih = (const float*)d_in[11];
    const float* W_hh = (const float*)d_in[12];
    const float* b_ih = (const float*)d_in[13];
    const float* b_hh = (const float*)d_in[14];
    const float* Wfc  = (const float*)d_in[15];
    const float* bfc  = (const float*)d_in[16];
    float* out = (float*)d_out;

    init_h_kernel<<<256, 256>>>(h0);
    precompute_M_kernel<<<192, 256>>>(W_ih, W4, b4, b_ih);
    precompute_w2_kernel<<<dim3(96, 8), 256>>>(dx, W2, b2);

    for (int t = 0; t < TT; t++) {
        stepA_kernel<<<128, 256>>>(W1, W_hh);
        stepB_kernel<<<128, 256>>>(dx, xin, W3, b1, b3, out, t);
        stepC_kernel<<<128, 256>>>(b_hh);
    }
    final_kernel<<<128, 256>>>(Wfc, bfc, out);
}

// round 8
// speedup vs baseline: 1.2422x; 1.2422x over previous
#include <cuda_runtime.h>

// Decoder: 48-step attention + GRU.  B=128, T=48, I=128, H=512.
//
// Restructurings:
//   - w2 = decoder_x @ W2^T + b2 precomputed once ([128,48,512]).
//   - M = W_ih @ W4 ([1536,131]), bM = W_ih@b4 + b_ih precomputed once,
//     so gi = u @ M^T + bM (exact fusion of two chained GEMMs).
//   - W^T = [W1 ; W_hh]^T precomputed ([512,2048]) and h^T maintained by
//     stepC, so stepA is a pure outer-product GEMM with float4 smem tiles.
// Per step (3 kernels):
//   A: hw = h @ [W1 ; W_hh]^T   (64 col-tiles x 4 k-split partials)
//   B: per-batch attention: w1 = sum(hw)+b1, e = tanh(w1+w2)@W3, softmax,
//      context c, u = [c, x_t] stored transposed uT[k][b]
//   C: gi = u@M^T + bM, GRU gates with gh = sum(hw)+b_hh, h update (+ h^T)
// Finale: re = h @ Wfc^T + bfc.
// Output: d_out[0:128] = re, d_out[128:128+6144] = alpha (last step).

#define BB 128
#define TT 48
#define II 128
#define HH 512
#define G3H 1536
#define CW 2048    // H + 3H columns of hw
#define UK 131     // I + 3
#define MST 132    // padded stride for M / uT rows

// ---------------- device scratch -------------------------------------------
__device__ float g_w2[BB * TT * HH];
__device__ float g_M[G3H * MST];
__device__ float g_bM[G3H];
__device__ float g_h[BB * HH];       // h[b][k]
__device__ float g_hT[HH * BB];      // h^T[k][b]
__device__ float g_WT[HH * CW];      // [W1;W_hh]^T : WT[k][c]
__device__ float g_hw[4][BB * CW];   // 4 k-split partials of h @ Wcomb^T
__device__ float g_uT[MST * BB];     // u^T[k][b]

// ---------------- fast math -------------------------------------------------
__device__ __forceinline__ float fast_tanh(float x) {
    float e = __expf(2.0f * x);
    return 1.0f - __fdividef(2.0f, e + 1.0f);
}
__device__ __forceinline__ float fast_sigmoid(float x) {
    return __fdividef(1.0f, 1.0f + __expf(-x));
}

// ---------------- init h + h^T ----------------------------------------------
__global__ __launch_bounds__(256) void init_h_kernel(const float* __restrict__ h0) {
    int i = blockIdx.x * 256 + threadIdx.x;
    if (i < BB * HH) {
        int b = i >> 9, k = i & (HH - 1);
        float v = h0[i];
        g_h[i] = v;
        g_hT[k * BB + b] = v;
    }
}

// ---------------- precompute W^T (tiled transpose) --------------------------
// grid (64, 16): source is [2048 rows c][512 cols k]; dest WT[k][c].
__global__ __launch_bounds__(256) void precompute_WT_kernel(
    const float* __restrict__ W1, const float* __restrict__ W_hh) {
    __shared__ float tile[32][33];
    int cb = blockIdx.x * 32;
    int kb = blockIdx.y * 32;
    int tx = threadIdx.x & 31, ty = threadIdx.x >> 5;   // ty 0..7
    for (int r = ty; r < 32; r += 8) {
        int c = cb + r;
        const float* src = (c < HH) ? (W1 + c * HH) : (W_hh + (c - HH) * HH);
        tile[r][tx] = src[kb + tx];
    }
    __syncthreads();
    for (int r = ty; r < 32; r += 8)
        g_WT[(kb + r) * CW + cb + tx] = tile[tx][r];
}

// ---------------- precompute M = W_ih @ W4, bM ------------------------------
__global__ __launch_bounds__(256) void precompute_M_kernel(
    const float* __restrict__ W_ih, const float* __restrict__ W4,
    const float* __restrict__ b4,   const float* __restrict__ b_ih) {
    __shared__ float sW[8][HH + 1];
    int g0 = blockIdx.x * 8;
    int tid = threadIdx.x;
    for (int i = tid; i < 8 * HH; i += 256) {
        int r = i >> 9, h = i & (HH - 1);
        sW[r][h] = W_ih[(g0 + r) * HH + h];
    }
    __syncthreads();
    int j = tid;
    if (j < 132) {
        float acc[8];
#pragma unroll
        for (int r = 0; r < 8; r++) acc[r] = 0.0f;
        for (int h = 0; h < HH; h++) {
            float bv = (j < UK) ? W4[h * UK + j] : b4[h];
#pragma unroll
            for (int r = 0; r < 8; r++) acc[r] += sW[r][h] * bv;
        }
#pragma unroll
        for (int r = 0; r < 8; r++) {
            int g = g0 + r;
            if (j < UK) g_M[g * MST + j] = acc[r];
            else        g_bM[g] = acc[r] + b_ih[g];
        }
    }
}

// ---------------- precompute w2 ---------------------------------------------
__global__ __launch_bounds__(256) void precompute_w2_kernel(
    const float* __restrict__ dx, const float* __restrict__ W2,
    const float* __restrict__ b2) {
    __shared__ float As[64][65];
    __shared__ float Bs[64][65];
    int r0 = blockIdx.x * 64;
    int c0 = blockIdx.y * 64;
    int tid = threadIdx.x;
    int tx = tid & 15, ty = tid >> 4;
    int c4 = tx * 4, r4 = ty * 4;
    float acc[4][4] = {};
    for (int kc = 0; kc < 2; kc++) {
        int k0 = kc * 64;
        for (int i = tid; i < 64 * 64; i += 256) {
            int r = i >> 6, kk = i & 63;
            As[r][kk] = dx[(r0 + r) * II + k0 + kk];
            Bs[r][kk] = W2[(c0 + r) * II + k0 + kk];
        }
        __syncthreads();
#pragma unroll 8
        for (int kk = 0; kk < 64; kk++) {
            float w0 = Bs[c4 + 0][kk], w1 = Bs[c4 + 1][kk];
            float w2 = Bs[c4 + 2][kk], w3 = Bs[c4 + 3][kk];
#pragma unroll
            for (int i = 0; i < 4; i++) {
                float hv = As[r4 + i][kk];
                acc[i][0] += hv * w0; acc[i][1] += hv * w1;
                acc[i][2] += hv * w2; acc[i][3] += hv * w3;
            }
        }
        __syncthreads();
    }
#pragma unroll
    for (int i = 0; i < 4; i++)
#pragma unroll
        for (int j = 0; j < 4; j++)
            g_w2[(r0 + r4 + i) * HH + c0 + c4 + j] = acc[i][j] + b2[c0 + c4 + j];
}

// ---------------- step A: hw partials = h @ [W1;W_hh]^T ---------------------
// 256 blocks = 64 col-tiles (32 cols) x 4 k-splits (128 k each).
// Operands pre-transposed: pure float4 smem, 2 LDS.128 + 16 FFMA per k.
__global__ __launch_bounds__(256) void stepA_kernel() {
    __shared__ float4 HS[32][32];   // [kk][b/4] : 128 batch floats per k row
    __shared__ float4 WS[32][8];    // [kk][c/4] : 32 col floats per k row
    int ct = blockIdx.x & 63, kt = blockIdx.x >> 6;
    int c0 = ct * 32;
    int kbase = kt * 128;
    float* out = g_hw[kt];
    int tid = threadIdx.x;
    int tx = tid & 7, ty = tid >> 3;   // c4 = 4*tx, r4 = 4*ty
    float acc[4][4] = {};

    for (int kc = 0; kc < 4; kc++) {
        int k0 = kbase + kc * 32;
        for (int i = tid; i < 1024; i += 256) {
            int kk = i >> 5, rq = i & 31;
            HS[kk][rq] = ((const float4*)g_hT)[(k0 + kk) * (BB / 4) + rq];
        }
        {
            int kk = tid >> 3, cq = tid & 7;
            WS[kk][cq] = ((const float4*)g_WT)[(k0 + kk) * (CW / 4) + (c0 >> 2) + cq];
        }
        __syncthreads();
#pragma unroll
        for (int kk = 0; kk < 32; kk++) {
            float4 hv = HS[kk][ty];
            float4 wv = WS[kk][tx];
            acc[0][0] += hv.x * wv.x; acc[0][1] += hv.x * wv.y;
            acc[0][2] += hv.x * wv.z; acc[0][3] += hv.x * wv.w;
            acc[1][0] += hv.y * wv.x; acc[1][1] += hv.y * wv.y;
            acc[1][2] += hv.y * wv.z; acc[1][3] += hv.y * wv.w;
            acc[2][0] += hv.z * wv.x; acc[2][1] += hv.z * wv.y;
            acc[2][2] += hv.z * wv.z; acc[2][3] += hv.z * wv.w;
            acc[3][0] += hv.w * wv.x; acc[3][1] += hv.w * wv.y;
            acc[3][2] += hv.w * wv.z; acc[3][3] += hv.w * wv.w;
        }
        __syncthreads();
    }
    float* orow = out + (ty * 4) * CW + c0 + tx * 4;
#pragma unroll
    for (int i = 0; i < 4; i++)
        *(float4*)(orow + i * CW) =
            make_float4(acc[i][0], acc[i][1], acc[i][2], acc[i][3]);
}

// ---------------- step B: attention + context + uT --------------------------
__global__ __launch_bounds__(256) void stepB_kernel(
    const float* __restrict__ dx, const float* __restrict__ xin,
    const float* __restrict__ W3, const float* __restrict__ b1,
    const float* __restrict__ b3, float* __restrict__ out, int step) {
    __shared__ float w1s[HH];
    __shared__ float w3s[HH];
    __shared__ float es[TT];
    int b = blockIdx.x;
    int tid = threadIdx.x;
    for (int i = tid; i < HH; i += 256) {
        int o = b * CW + i;
        w1s[i] = g_hw[0][o] + g_hw[1][o] + g_hw[2][o] + g_hw[3][o] + b1[i];
        w3s[i] = W3[i];
    }
    __syncthreads();

    int warp = tid >> 5, lane = tid & 31;
    float b3v = b3[0];
    for (int j = 0; j < 6; j++) {
        int t = warp * 6 + j;
        const float* w2p = g_w2 + (b * TT + t) * HH + lane;
        float wv[16];
#pragma unroll
        for (int q = 0; q < 16; q++) wv[q] = w2p[q * 32];   // MLP=16
        float p = 0.0f;
#pragma unroll
        for (int q = 0; q < 16; q++) {
            int h = lane + q * 32;
            p += fast_tanh(w1s[h] + wv[q]) * w3s[h];
        }
#pragma unroll
        for (int o = 16; o > 0; o >>= 1) p += __shfl_down_sync(0xffffffffu, p, o);
        if (lane == 0) es[t] = p + b3v;
    }
    __syncthreads();

    if (warp == 0) {
        float m = -1e30f;
        for (int i = lane; i < TT; i += 32) m = fmaxf(m, es[i]);
#pragma unroll
        for (int o = 16; o > 0; o >>= 1) m = fmaxf(m, __shfl_xor_sync(0xffffffffu, m, o));
        float s = 0.0f;
        for (int i = lane; i < TT; i += 32) { float e = __expf(es[i] - m); es[i] = e; s += e; }
#pragma unroll
        for (int o = 16; o > 0; o >>= 1) s += __shfl_xor_sync(0xffffffffu, s, o);
        float inv = __fdividef(1.0f, s);
        for (int i = lane; i < TT; i += 32) es[i] *= inv;
    }
    __syncthreads();

    if (tid < II) {
        const float* dp = dx + b * TT * II + tid;
        float acc = 0.0f;
#pragma unroll 8
        for (int t = 0; t < TT; t++) acc += dp[t * II] * es[t];
        g_uT[tid * BB + b] = acc;
    } else if (tid < UK) {
        int j = tid - II;
        g_uT[(II + j) * BB + b] = xin[(b * TT + step) * 3 + j];
    }
    if (step == TT - 1 && tid < TT)
        out[BB + b * TT + tid] = es[tid];
}

// ---------------- step C: gi = u @ M^T + bM, GRU update ---------------------
// 128 blocks; block j handles h-columns [4j, 4j+4). Also maintains h^T.
__global__ __launch_bounds__(256) void stepC_kernel(const float* __restrict__ b_hh) {
    __shared__ float Ms[12][MST];
    __shared__ __align__(16) float us[32][BB];
    int jb = blockIdx.x;
    int c0 = jb * 4;
    int tid = threadIdx.x;
    for (int i = tid; i < 12 * MST; i += 256) {
        int rr = i / MST, k = i - rr * MST;
        int g4 = rr / 3, gate = rr - g4 * 3;
        int gr = gate * HH + c0 + g4;
        Ms[rr][k] = (k < UK) ? g_M[gr * MST + k] : 0.0f;
    }
    __syncthreads();

    int bp = tid & 63;
    int g4 = tid >> 6;
    float acc[2][3] = {};

    for (int kc = 0; kc < 5; kc++) {
        int kbase = kc * 32;
        for (int i = tid; i < 32 * BB; i += 256) {
            int kk = i >> 7, bb = i & 127;
            int kg = kbase + kk;
            us[kk][bb] = (kg < UK) ? g_uT[kg * BB + bb] : 0.0f;
        }
        __syncthreads();
        int kmax = UK - kbase; if (kmax > 32) kmax = 32;
#pragma unroll 8
        for (int kk = 0; kk < kmax; kk++) {
            float2 uv = *(const float2*)&us[kk][bp * 2];
            int kg = kbase + kk;
            float m0 = Ms[g4 * 3 + 0][kg];
            float m1 = Ms[g4 * 3 + 1][kg];
            float m2 = Ms[g4 * 3 + 2][kg];
            acc[0][0] += uv.x * m0; acc[0][1] += uv.x * m1; acc[0][2] += uv.x * m2;
            acc[1][0] += uv.y * m0; acc[1][1] += uv.y * m1; acc[1][2] += uv.y * m2;
        }
        __syncthreads();
    }

    int c = c0 + g4;
#pragma unroll
    for (int bi = 0; bi < 2; bi++) {
        int b = bp * 2 + bi;
        float gir = acc[bi][0] + g_bM[c];
        float giz = acc[bi][1] + g_bM[HH + c];
        float gin = acc[bi][2] + g_bM[2 * HH + c];
        int o = b * CW + HH;
        float ghr = g_hw[0][o + c] + g_hw[1][o + c] + g_hw[2][o + c] + g_hw[3][o + c] + b_hh[c];
        float ghz = g_hw[0][o + HH + c] + g_hw[1][o + HH + c] + g_hw[2][o + HH + c] + g_hw[3][o + HH + c] + b_hh[HH + c];
        float ghn = g_hw[0][o + 2 * HH + c] + g_hw[1][o + 2 * HH + c] + g_hw[2][o + 2 * HH + c] + g_hw[3][o + 2 * HH + c] + b_hh[2 * HH + c];
        float r = fast_sigmoid(gir + ghr);
        float z = fast_sigmoid(giz + ghz);
        float n = fast_tanh(gin + r * ghn);
        float hold = g_h[b * HH + c];
        float hnew = (1.0f - z) * n + z * hold;
        g_h[b * HH + c] = hnew;
        g_hT[c * BB + b] = hnew;
    }
}

// ---------------- finale ----------------------------------------------------
__global__ __launch_bounds__(256) void final_kernel(
    const float* __restrict__ Wfc, const float* __restrict__ bfc,
    float* __restrict__ out) {
    __shared__ float red[8];
    int b = blockIdx.x;
    int tid = threadIdx.x;
    int warp = tid >> 5, lane = tid & 31;
    float p = 0.0f;
    for (int h = tid; h < HH; h += 256) p += g_h[b * HH + h] * Wfc[h];
#pragma unroll
    for (int o = 16; o > 0; o >>= 1) p += __shfl_down_sync(0xffffffffu, p, o);
    if (lane == 0) red[warp] = p;
    __syncthreads();
    if (tid == 0) {
        float s = 0.0f;
#pragma unroll
        for (int w = 0; w < 8; w++) s += red[w];
        out[b] = s + bfc[0];
    }
}

// ---------------- launcher --------------------------------------------------
extern "C" void kernel_launch(void* const* d_in, const int* in_sizes, int n_in,
                              void* d_out, int out_size) {
    (void)in_sizes; (void)n_in; (void)out_size;
    const float* dx   = (const float*)d_in[0];
    const float* xin  = (const float*)d_in[1];
    const float* h0   = (const float*)d_in[2];
    const float* W1   = (const float*)d_in[3];
    const float* b1   = (const float*)d_in[4];
    const float* W2   = (const float*)d_in[5];
    const float* b2   = (const float*)d_in[6];
    const float* W3   = (const float*)d_in[7];
    const float* b3   = (const float*)d_in[8];
    const float* W4   = (const float*)d_in[9];
    const float* b4   = (const float*)d_in[10];
    const float* W_ih = (const float*)d_in[11];
    const float* W_hh = (const float*)d_in[12];
    const float* b_ih = (const float*)d_in[13];
    const float* b_hh = (const float*)d_in[14];
    const float* Wfc  = (const float*)d_in[15];
    const float* bfc  = (const float*)d_in[16];
    float* out = (float*)d_out;

    init_h_kernel<<<256, 256>>>(h0);
    precompute_WT_kernel<<<dim3(64, 16), 256>>>(W1, W_hh);
    precompute_M_kernel<<<192, 256>>>(W_ih, W4, b4, b_ih);
    precompute_w2_kernel<<<dim3(96, 8), 256>>>(dx, W2, b2);

    for (int t = 0; t < TT; t++) {
        stepA_kernel<<<256, 256>>>();
        stepB_kernel<<<128, 256>>>(dx, xin, W3, b1, b3, out, t);
        stepC_kernel<<<128, 256>>>(b_hh);
    }
    final_kernel<<<128, 256>>>(Wfc, bfc, out);
}

// round 9
// speedup vs baseline: 1.7101x; 1.3767x over previous
#include <cuda_runtime.h>

// Decoder: 48-step attention + GRU.  B=128, T=48, I=128, H=512.
//
// Restructurings:
//   - w2 = decoder_x @ W2^T + b2 precomputed once ([128,48,512]).
//   - M = W_ih @ W4 ([1536,131]), bM = W_ih@b4 + b_ih precomputed once,
//     so gi = u @ M^T + bM (exact fusion of two chained GEMMs).
//   - W^T = [W1 ; W_hh]^T precomputed ([512,2048]); h^T maintained in-loop.
//   - ENTIRE 48-step loop runs in ONE persistent kernel (128 blocks x 256
//     threads, all co-resident) with a global atomic barrier between phases:
//       A: hw = h @ [W1;W_hh]^T  (64 col-tiles x 2 k-halves = 128 blocks)
//       B: attention -> softmax -> context -> uT   (block = batch)
//       C: gi = u@M^T + bM, GRU gates, h update    (block = 4 h-columns)
//     Finale re = h @ Wfc^T + bfc in the same kernel.
// Output: d_out[0:128] = re, d_out[128:128+6144] = alpha (last step).

#define BB 128
#define TT 48
#define II 128
#define HH 512
#define G3H 1536
#define CW 2048    // H + 3H columns of hw
#define UK 131     // I + 3
#define MST 132    // padded stride for M / uT rows
#define GRID 128

// ---------------- device scratch -------------------------------------------
__device__ __align__(16) float g_w2[BB * TT * HH];
__device__ __align__(16) float g_M[G3H * MST];
__device__ __align__(16) float g_bM[G3H];
__device__ __align__(16) float g_h[BB * HH];     // h[b][k]
__device__ __align__(16) float g_hT[HH * BB];    // h^T[k][b]
__device__ __align__(16) float g_WT[HH * CW];    // [W1;W_hh]^T : WT[k][c]
__device__ __align__(16) float g_hw[2][BB * CW]; // 2 k-split partials
__device__ __align__(16) float g_uT[MST * BB];   // u^T[k][b]
__device__ unsigned int g_bar;                   // grid barrier counter

// ---------------- fast math -------------------------------------------------
__device__ __forceinline__ float fast_tanh(float x) {
    float e = __expf(2.0f * x);
    return 1.0f - __fdividef(2.0f, e + 1.0f);
}
__device__ __forceinline__ float fast_sigmoid(float x) {
    return __fdividef(1.0f, 1.0f + __expf(-x));
}

// ---------------- grid barrier (all 128 blocks co-resident) -----------------
__device__ __forceinline__ void grid_bar(unsigned int& target) {
    __syncthreads();
    if (threadIdx.x == 0) {
        __threadfence();                       // release (CCTL.IVALL, gpu scope)
        atomicAdd(&g_bar, 1u);
        target += GRID;
        while ((int)(atomicAdd(&g_bar, 0u) - target) < 0) {}
        __threadfence();                       // acquire: invalidate stale L1
    }
    __syncthreads();
}

// ---------------- init h + h^T + barrier reset ------------------------------
__global__ __launch_bounds__(256) void init_h_kernel(const float* __restrict__ h0) {
    if (blockIdx.x == 0 && threadIdx.x == 0) g_bar = 0u;
    int i = blockIdx.x * 256 + threadIdx.x;
    if (i < BB * HH) {
        int b = i >> 9, k = i & (HH - 1);
        float v = h0[i];
        g_h[i] = v;
        g_hT[k * BB + b] = v;
    }
}

// ---------------- precompute W^T (tiled transpose) --------------------------
__global__ __launch_bounds__(256) void precompute_WT_kernel(
    const float* __restrict__ W1, const float* __restrict__ W_hh) {
    __shared__ float tile[32][33];
    int cb = blockIdx.x * 32;
    int kb = blockIdx.y * 32;
    int tx = threadIdx.x & 31, ty = threadIdx.x >> 5;
    for (int r = ty; r < 32; r += 8) {
        int c = cb + r;
        const float* src = (c < HH) ? (W1 + c * HH) : (W_hh + (c - HH) * HH);
        tile[r][tx] = src[kb + tx];
    }
    __syncthreads();
    for (int r = ty; r < 32; r += 8)
        g_WT[(kb + r) * CW + cb + tx] = tile[tx][r];
}

// ---------------- precompute M = W_ih @ W4, bM ------------------------------
__global__ __launch_bounds__(256) void precompute_M_kernel(
    const float* __restrict__ W_ih, const float* __restrict__ W4,
    const float* __restrict__ b4,   const float* __restrict__ b_ih) {
    __shared__ float sW[8][HH + 1];
    int g0 = blockIdx.x * 8;
    int tid = threadIdx.x;
    for (int i = tid; i < 8 * HH; i += 256) {
        int r = i >> 9, h = i & (HH - 1);
        sW[r][h] = W_ih[(g0 + r) * HH + h];
    }
    __syncthreads();
    int j = tid;
    if (j < 132) {
        float acc[8];
#pragma unroll
        for (int r = 0; r < 8; r++) acc[r] = 0.0f;
        for (int h = 0; h < HH; h++) {
            float bv = (j < UK) ? W4[h * UK + j] : b4[h];
#pragma unroll
            for (int r = 0; r < 8; r++) acc[r] += sW[r][h] * bv;
        }
#pragma unroll
        for (int r = 0; r < 8; r++) {
            int g = g0 + r;
            if (j < UK) g_M[g * MST + j] = acc[r];
            else        g_bM[g] = acc[r] + b_ih[g];
        }
    }
}

// ---------------- precompute w2 ---------------------------------------------
__global__ __launch_bounds__(256) void precompute_w2_kernel(
    const float* __restrict__ dx, const float* __restrict__ W2,
    const float* __restrict__ b2) {
    __shared__ float As[64][65];
    __shared__ float Bs[64][65];
    int r0 = blockIdx.x * 64;
    int c0 = blockIdx.y * 64;
    int tid = threadIdx.x;
    int tx = tid & 15, ty = tid >> 4;
    int c4 = tx * 4, r4 = ty * 4;
    float acc[4][4] = {};
    for (int kc = 0; kc < 2; kc++) {
        int k0 = kc * 64;
        for (int i = tid; i < 64 * 64; i += 256) {
            int r = i >> 6, kk = i & 63;
            As[r][kk] = dx[(r0 + r) * II + k0 + kk];
            Bs[r][kk] = W2[(c0 + r) * II + k0 + kk];
        }
        __syncthreads();
#pragma unroll 8
        for (int kk = 0; kk < 64; kk++) {
            float w0 = Bs[c4 + 0][kk], w1 = Bs[c4 + 1][kk];
            float w2 = Bs[c4 + 2][kk], w3 = Bs[c4 + 3][kk];
#pragma unroll
            for (int i = 0; i < 4; i++) {
                float hv = As[r4 + i][kk];
                acc[i][0] += hv * w0; acc[i][1] += hv * w1;
                acc[i][2] += hv * w2; acc[i][3] += hv * w3;
            }
        }
        __syncthreads();
    }
#pragma unroll
    for (int i = 0; i < 4; i++)
#pragma unroll
        for (int j = 0; j < 4; j++)
            g_w2[(r0 + r4 + i) * HH + c0 + c4 + j] = acc[i][j] + b2[c0 + c4 + j];
}

// ---------------- persistent 48-step loop kernel ----------------------------
__global__ __launch_bounds__(256, 1) void decoder_loop_kernel(
    const float* __restrict__ dx, const float* __restrict__ xin,
    const float* __restrict__ W3, const float* __restrict__ b1,
    const float* __restrict__ b3, const float* __restrict__ b_hh,
    const float* __restrict__ Wfc, const float* __restrict__ bfc,
    float* __restrict__ out) {
    __shared__ __align__(16) unsigned char smraw[24576];
    int tid = threadIdx.x;
    int bid = blockIdx.x;
    unsigned int bar_target = 0;

    // phase A views
    float4 (*HS)[32] = (float4(*)[32])smraw;             // [32 kk][32 b/4]
    float4 (*WS)[8]  = (float4(*)[8])(smraw + 16384);    // [32 kk][8 c/4]
    // phase B views
    float* w1s = (float*)smraw;                          // [512]
    float* w3s = (float*)(smraw + 2048);                 // [512]
    float* es  = (float*)(smraw + 4096);                 // [48]
    // phase C views
    float (*us)[BB]  = (float(*)[BB])smraw;              // [32][128]
    float (*Ms)[MST] = (float(*)[MST])(smraw + 16384);   // [12][132]

    // phase-A block mapping: 64 col-tiles x 2 k-halves
    const int ct = bid & 63, kt = bid >> 6;
    const int c0A = ct * 32;
    const int kbase = kt * 256;
    const int txA = tid & 7, tyA = tid >> 3;
    // phase-C block mapping
    const int c0C = bid * 4;
    const int warp = tid >> 5, lane = tid & 31;

    for (int t = 0; t < TT; t++) {
        // ================= phase A: hw[kt] = h @ WT (k-half) ================
        {
            float acc[4][4] = {};
            float4 ph[4]; float4 pw;
            // prefetch chunk 0
#pragma unroll
            for (int q = 0; q < 4; q++) {
                int i = tid + q * 256; int kk = i >> 5, rq = i & 31;
                ph[q] = ((const float4*)g_hT)[(kbase + kk) * (BB / 4) + rq];
            }
            pw = ((const float4*)g_WT)[(kbase + (tid >> 3)) * (CW / 4) + (c0A >> 2) + (tid & 7)];
#pragma unroll
            for (int q = 0; q < 4; q++) {
                int i = tid + q * 256; HS[i >> 5][i & 31] = ph[q];
            }
            WS[tid >> 3][tid & 7] = pw;
            __syncthreads();

            for (int kc = 0; kc < 8; kc++) {
                float4 nh[4]; float4 nw;
                if (kc < 7) {
                    int k0n = kbase + (kc + 1) * 32;
#pragma unroll
                    for (int q = 0; q < 4; q++) {
                        int i = tid + q * 256; int kk = i >> 5, rq = i & 31;
                        nh[q] = ((const float4*)g_hT)[(k0n + kk) * (BB / 4) + rq];
                    }
                    nw = ((const float4*)g_WT)[(k0n + (tid >> 3)) * (CW / 4) + (c0A >> 2) + (tid & 7)];
                }
#pragma unroll
                for (int kk = 0; kk < 32; kk++) {
                    float4 hv = HS[kk][tyA];
                    float4 wv = WS[kk][txA];
                    acc[0][0] += hv.x * wv.x; acc[0][1] += hv.x * wv.y;
                    acc[0][2] += hv.x * wv.z; acc[0][3] += hv.x * wv.w;
                    acc[1][0] += hv.y * wv.x; acc[1][1] += hv.y * wv.y;
                    acc[1][2] += hv.y * wv.z; acc[1][3] += hv.y * wv.w;
                    acc[2][0] += hv.z * wv.x; acc[2][1] += hv.z * wv.y;
                    acc[2][2] += hv.z * wv.z; acc[2][3] += hv.z * wv.w;
                    acc[3][0] += hv.w * wv.x; acc[3][1] += hv.w * wv.y;
                    acc[3][2] += hv.w * wv.z; acc[3][3] += hv.w * wv.w;
                }
                __syncthreads();
                if (kc < 7) {
#pragma unroll
                    for (int q = 0; q < 4; q++) {
                        int i = tid + q * 256; HS[i >> 5][i & 31] = nh[q];
                    }
                    WS[tid >> 3][tid & 7] = nw;
                }
                __syncthreads();
            }
            float* orow = g_hw[kt] + (tyA * 4) * CW + c0A + txA * 4;
#pragma unroll
            for (int i = 0; i < 4; i++)
                *(float4*)(orow + i * CW) =
                    make_float4(acc[i][0], acc[i][1], acc[i][2], acc[i][3]);
        }
        grid_bar(bar_target);

        // ================= phase B: attention (block = batch bid) ===========
        {
            int b = bid;
            for (int i = tid; i < HH; i += 256) {
                int o = b * CW + i;
                w1s[i] = g_hw[0][o] + g_hw[1][o] + b1[i];
                w3s[i] = W3[i];
            }
            __syncthreads();

            float b3v = b3[0];
            for (int j = 0; j < 6; j++) {
                int tt = warp * 6 + j;
                const float* w2p = g_w2 + (b * TT + tt) * HH + lane;
                float wv[16];
#pragma unroll
                for (int q = 0; q < 16; q++) wv[q] = w2p[q * 32];
                float p = 0.0f;
#pragma unroll
                for (int q = 0; q < 16; q++) {
                    int h = lane + q * 32;
                    p += fast_tanh(w1s[h] + wv[q]) * w3s[h];
                }
#pragma unroll
                for (int o = 16; o > 0; o >>= 1) p += __shfl_down_sync(0xffffffffu, p, o);
                if (lane == 0) es[tt] = p + b3v;
            }
            __syncthreads();

            if (warp == 0) {
                float m = -1e30f;
                for (int i = lane; i < TT; i += 32) m = fmaxf(m, es[i]);
#pragma unroll
                for (int o = 16; o > 0; o >>= 1) m = fmaxf(m, __shfl_xor_sync(0xffffffffu, m, o));
                float s = 0.0f;
                for (int i = lane; i < TT; i += 32) { float e = __expf(es[i] - m); es[i] = e; s += e; }
#pragma unroll
                for (int o = 16; o > 0; o >>= 1) s += __shfl_xor_sync(0xffffffffu, s, o);
                float inv = __fdividef(1.0f, s);
                for (int i = lane; i < TT; i += 32) es[i] *= inv;
            }
            __syncthreads();

            if (tid < II) {
                const float* dp = dx + b * TT * II + tid;
                float acc = 0.0f;
#pragma unroll 8
                for (int tt2 = 0; tt2 < TT; tt2++) acc += dp[tt2 * II] * es[tt2];
                g_uT[tid * BB + b] = acc;
            } else if (tid < UK) {
                int j = tid - II;
                g_uT[(II + j) * BB + b] = xin[(b * TT + t) * 3 + j];
            }
            if (t == TT - 1 && tid < TT)
                out[BB + b * TT + tid] = es[tid];
            __syncthreads();
        }
        grid_bar(bar_target);

        // ================= phase C: GRU (block = 4 h-columns) ===============
        {
            for (int i = tid; i < 12 * MST; i += 256) {
                int rr = i / MST, k = i - rr * MST;
                int g4 = rr / 3, gate = rr - g4 * 3;
                int gr = gate * HH + c0C + g4;
                Ms[rr][k] = (k < UK) ? g_M[gr * MST + k] : 0.0f;
            }
            __syncthreads();

            int bp = tid & 63;
            int g4 = tid >> 6;
            float acc[2][3] = {};

            for (int kc = 0; kc < 5; kc++) {
                int kb2 = kc * 32;
                for (int i = tid; i < 32 * BB; i += 256) {
                    int kk = i >> 7, bb = i & 127;
                    int kg = kb2 + kk;
                    us[kk][bb] = (kg < UK) ? g_uT[kg * BB + bb] : 0.0f;
                }
                __syncthreads();
                int kmax = UK - kb2; if (kmax > 32) kmax = 32;
#pragma unroll 8
                for (int kk = 0; kk < kmax; kk++) {
                    float2 uv = *(const float2*)&us[kk][bp * 2];
                    int kg = kb2 + kk;
                    float m0 = Ms[g4 * 3 + 0][kg];
                    float m1 = Ms[g4 * 3 + 1][kg];
                    float m2 = Ms[g4 * 3 + 2][kg];
                    acc[0][0] += uv.x * m0; acc[0][1] += uv.x * m1; acc[0][2] += uv.x * m2;
                    acc[1][0] += uv.y * m0; acc[1][1] += uv.y * m1; acc[1][2] += uv.y * m2;
                }
                __syncthreads();
            }

            int c = c0C + g4;
#pragma unroll
            for (int bi = 0; bi < 2; bi++) {
                int b = bp * 2 + bi;
                float gir = acc[bi][0] + g_bM[c];
                float giz = acc[bi][1] + g_bM[HH + c];
                float gin = acc[bi][2] + g_bM[2 * HH + c];
                int o = b * CW + HH;
                float ghr = g_hw[0][o + c] + g_hw[1][o + c] + b_hh[c];
                float ghz = g_hw[0][o + HH + c] + g_hw[1][o + HH + c] + b_hh[HH + c];
                float ghn = g_hw[0][o + 2 * HH + c] + g_hw[1][o + 2 * HH + c] + b_hh[2 * HH + c];
                float r = fast_sigmoid(gir + ghr);
                float z = fast_sigmoid(giz + ghz);
                float n = fast_tanh(gin + r * ghn);
                float hold = g_h[b * HH + c];
                float hnew = (1.0f - z) * n + z * hold;
                g_h[b * HH + c] = hnew;
                g_hT[c * BB + b] = hnew;
            }
        }
        grid_bar(bar_target);
    }

    // ================= finale: re = h @ Wfc^T + bfc (block = batch) =========
    {
        float* red = (float*)smraw;
        int b = bid;
        float p = 0.0f;
        for (int h = tid; h < HH; h += 256) p += g_h[b * HH + h] * Wfc[h];
#pragma unroll
        for (int o = 16; o > 0; o >>= 1) p += __shfl_down_sync(0xffffffffu, p, o);
        if (lane == 0) red[warp] = p;
        __syncthreads();
        if (tid == 0) {
            float s = 0.0f;
#pragma unroll
            for (int w = 0; w < 8; w++) s += red[w];
            out[b] = s + bfc[0];
        }
    }
}

// ---------------- launcher --------------------------------------------------
extern "C" void kernel_launch(void* const* d_in, const int* in_sizes, int n_in,
                              void* d_out, int out_size) {
    (void)in_sizes; (void)n_in; (void)out_size;
    const float* dx   = (const float*)d_in[0];
    const float* xin  = (const float*)d_in[1];
    const float* h0   = (const float*)d_in[2];
    const float* W1   = (const float*)d_in[3];
    const float* b1   = (const float*)d_in[4];
    const float* W2   = (const float*)d_in[5];
    const float* b2   = (const float*)d_in[6];
    const float* W3   = (const float*)d_in[7];
    const float* b3   = (const float*)d_in[8];
    const float* W4   = (const float*)d_in[9];
    const float* b4   = (const float*)d_in[10];
    const float* W_ih = (const float*)d_in[11];
    const float* W_hh = (const float*)d_in[12];
    const float* b_ih = (const float*)d_in[13];
    const float* b_hh = (const float*)d_in[14];
    const float* Wfc  = (const float*)d_in[15];
    const float* bfc  = (const float*)d_in[16];
    float* out = (float*)d_out;

    init_h_kernel<<<256, 256>>>(h0);
    precompute_WT_kernel<<<dim3(64, 16), 256>>>(W1, W_hh);
    precompute_M_kernel<<<192, 256>>>(W_ih, W4, b4, b_ih);
    precompute_w2_kernel<<<dim3(96, 8), 256>>>(dx, W2, b2);

    decoder_loop_kernel<<<GRID, 256>>>(dx, xin, W3, b1, b3, b_hh, Wfc, bfc, out);
}